// round 1
// baseline (speedup 1.0000x reference)
#include <cuda_runtime.h>

// Problem constants (fixed shapes per reference: B=128, C=1, H=W=512, BINS=256)
#define NBINS      256
#define HEIGHT_RT  0.05f
#define NB         128          // batch
#define NPER       262144       // 512*512 elems per sample
#define CHUNKS     8            // hist blocks per sample
#define CHUNK_EL   (NPER / CHUNKS)   // 32768 elems per hist block
#define OUT_X      ((size_t)NB * NPER)   // 33554432 floats of out, then NB values

// Scratch (no allocations allowed): partial histograms + per-sample scale w.
// Every slot of g_hist_partial is fully overwritten each call -> no zeroing pass.
__device__ unsigned int g_hist_partial[NB * CHUNKS * NBINS];   // 1 MB
__device__ float        g_w[NB];

// ---------------------------------------------------------------------------
// Kernel 1: per-(sample,chunk) histogram. grid = (CHUNKS, NB), 256 threads.
// Per-warp privatized smem histograms (8 copies) -> one global partial slice.
// ---------------------------------------------------------------------------
__global__ __launch_bounds__(256) void hist_kernel(const float* __restrict__ x) {
    __shared__ unsigned int sh[8][NBINS];
    const int tid    = threadIdx.x;          // 0..255
    const int warp   = tid >> 5;
    const int sample = blockIdx.y;
    const int chunk  = blockIdx.x;

    #pragma unroll
    for (int c = 0; c < 8; c++) sh[c][tid] = 0u;
    __syncthreads();

    const float4* __restrict__ p =
        (const float4*)(x + (size_t)sample * NPER + (size_t)chunk * CHUNK_EL);
    // CHUNK_EL/4 = 8192 float4 per block; 32 per thread
    #pragma unroll 8
    for (int j = 0; j < 32; j++) {
        float4 v = p[j * 256 + tid];
        float vals[4] = {v.x, v.y, v.z, v.w};
        #pragma unroll
        for (int k = 0; k < 4; k++) {
            float f = vals[k];
            if (f >= 0.0f && f <= 1.0f) {           // torch.histc: out-of-range ignored
                int b = (int)(f * 256.0f);          // floor (f >= 0)
                if (b > 255) b = 255;               // f == 1.0 -> last bin
                atomicAdd(&sh[warp][b], 1u);
            }
        }
    }
    __syncthreads();

    unsigned int s = 0;
    #pragma unroll
    for (int c = 0; c < 8; c++) s += sh[c][tid];
    g_hist_partial[((size_t)sample * CHUNKS + chunk) * NBINS + tid] = s;
}

// ---------------------------------------------------------------------------
// Kernel 2: per-sample threshold value + MLP. grid = NB blocks, 128 threads.
// ---------------------------------------------------------------------------
__global__ __launch_bounds__(128) void mlp_kernel(
    const float* __restrict__ W1, const float* __restrict__ b1,
    const float* __restrict__ W2, const float* __restrict__ b2,
    const float* __restrict__ W3, const float* __restrict__ b3,
    const float* __restrict__ W4, const float* __restrict__ b4,
    float* __restrict__ out_value)
{
    __shared__ float s_h[NBINS];
    __shared__ float s_h1[32];
    __shared__ float s_h2[64];
    __shared__ float s_h3[128];
    __shared__ float s_p[4];

    const int b   = blockIdx.x;
    const int tid = threadIdx.x;   // 0..127

    // Sum the 8 chunk partials -> float histogram in smem
    for (int bin = tid; bin < NBINS; bin += 128) {
        unsigned int s = 0;
        #pragma unroll
        for (int c = 0; c < CHUNKS; c++)
            s += g_hist_partial[((size_t)b * CHUNKS + c) * NBINS + bin];
        s_h[bin] = (float)s;
    }
    __syncthreads();

    // Threshold value (exact JAX semantics): first-occurrence argmax, then
    // first i >= argmax with hst[i] <= max*rate; default index 0 if none.
    if (tid == 0) {
        float mx = s_h[0];
        int   am = 0;
        for (int i = 1; i < NBINS; i++)
            if (s_h[i] > mx) { mx = s_h[i]; am = i; }   // strict > keeps first max
        const float ch = mx * HEIGHT_RT;
        int vi = 0;
        for (int i = am; i < NBINS; i++)
            if (!(s_h[i] > ch)) { vi = i; break; }       // first false cond
        out_value[b] = (float)vi / (float)NBINS;
    }

    // Layer 1: 256 -> 32
    if (tid < 32) {
        float acc = b1[tid];
        const float* w = W1 + tid * 256;
        #pragma unroll 8
        for (int k = 0; k < 256; k++) acc = fmaf(s_h[k], w[k], acc);
        s_h1[tid] = fmaxf(acc, 0.0f);
    }
    __syncthreads();

    // Layer 2: 32 -> 64
    if (tid < 64) {
        float acc = b2[tid];
        const float* w = W2 + tid * 32;
        #pragma unroll
        for (int k = 0; k < 32; k++) acc = fmaf(s_h1[k], w[k], acc);
        s_h2[tid] = fmaxf(acc, 0.0f);
    }
    __syncthreads();

    // Layer 3: 64 -> 128
    {
        float acc = b3[tid];
        const float* w = W3 + tid * 64;
        #pragma unroll
        for (int k = 0; k < 64; k++) acc = fmaf(s_h2[k], w[k], acc);
        s_h3[tid] = fmaxf(acc, 0.0f);
    }
    __syncthreads();

    // Layer 4: 128 -> 1 (reduction)
    float part = s_h3[tid] * W4[tid];
    #pragma unroll
    for (int o = 16; o > 0; o >>= 1)
        part += __shfl_down_sync(0xffffffffu, part, o);
    if ((tid & 31) == 0) s_p[tid >> 5] = part;
    __syncthreads();
    if (tid == 0)
        g_w[b] = s_p[0] + s_p[1] + s_p[2] + s_p[3] + b4[0];
}

// ---------------------------------------------------------------------------
// Kernel 3: out = x * w[sample]. grid = NB*64 blocks, 256 threads, float4 x4.
// Each block covers 1024 float4 = 4096 elems, fully inside one sample
// (sample boundary = 65536 float4; 64 blocks per sample).
// ---------------------------------------------------------------------------
__global__ __launch_bounds__(256) void scale_kernel(const float* __restrict__ x,
                                                    float* __restrict__ out)
{
    const int bid    = blockIdx.x;
    const int sample = bid >> 6;                  // 64 blocks per sample
    const float w    = __ldg(&g_w[sample]);

    const float4* __restrict__ xin = (const float4*)x   + (size_t)bid * 1024 + threadIdx.x;
    float4* __restrict__       o   = (float4*)out       + (size_t)bid * 1024 + threadIdx.x;
    #pragma unroll
    for (int j = 0; j < 4; j++) {
        float4 v = xin[j * 256];
        v.x *= w; v.y *= w; v.z *= w; v.w *= w;
        o[j * 256] = v;
    }
}

// ---------------------------------------------------------------------------
extern "C" void kernel_launch(void* const* d_in, const int* in_sizes, int n_in,
                              void* d_out, int out_size)
{
    const float* x  = (const float*)d_in[0];
    const float* W1 = (const float*)d_in[1];
    const float* b1 = (const float*)d_in[2];
    const float* W2 = (const float*)d_in[3];
    const float* b2 = (const float*)d_in[4];
    const float* W3 = (const float*)d_in[5];
    const float* b3 = (const float*)d_in[6];
    const float* W4 = (const float*)d_in[7];
    const float* b4 = (const float*)d_in[8];

    float* out       = (float*)d_out;
    float* out_value = out + OUT_X;   // value tensor lives after the big output

    dim3 hgrid(CHUNKS, NB);
    hist_kernel<<<hgrid, 256>>>(x);
    mlp_kernel<<<NB, 128>>>(W1, b1, W2, b2, W3, b3, W4, b4, out_value);
    scale_kernel<<<NB * 64, 256>>>(x, out);
    (void)in_sizes; (void)n_in; (void)out_size;
}

// round 3
// speedup vs baseline: 1.1303x; 1.1303x over previous
#include <cuda_runtime.h>

// Problem constants (fixed shapes per reference: B=128, C=1, H=W=512, BINS=256)
#define NBINS      256
#define HEIGHT_RT  0.05f
#define NB         128                 // batch
#define NPER       262144              // 512*512 elems per sample
#define CHUNKS     16                  // hist blocks per sample
#define CHUNK_EL   (NPER / CHUNKS)     // 16384 elems per hist block
#define OUT_X      ((size_t)NB * NPER) // big output, then NB values

// Scratch (no allocations allowed). Every slot fully overwritten each call.
__device__ unsigned int g_hist_partial[NB * CHUNKS * NBINS];   // 2 MB
__device__ float        g_w[NB];

// ---------------------------------------------------------------------------
// Kernel 1: per-(sample,chunk) histogram. grid = (CHUNKS, NB), 256 threads.
// Bank-conflict-free privatization: sh[bin][lane] -> lane l always touches
// bank l (addr = bin*32 + lane). Atomics only contend when two warps' same
// lane hits the same bin in the same cycle (rare for uniform data).
// ---------------------------------------------------------------------------
__global__ __launch_bounds__(256) void hist_kernel(const float* __restrict__ x) {
    __shared__ unsigned int sh[NBINS * 32];      // 32 KB: [bin][lane]
    const int tid    = threadIdx.x;              // 0..255
    const int lane   = tid & 31;
    const int sample = blockIdx.y;
    const int chunk  = blockIdx.x;

    #pragma unroll
    for (int i = 0; i < 32; i++) sh[i * 256 + tid] = 0u;
    __syncthreads();

    const float4* __restrict__ p =
        (const float4*)(x + (size_t)sample * NPER + (size_t)chunk * CHUNK_EL);
    // CHUNK_EL/4 = 4096 float4 per block; 16 per thread
    #pragma unroll 4
    for (int j = 0; j < 16; j++) {
        float4 v = __ldcs(p + j * 256 + tid);
        float vals[4] = {v.x, v.y, v.z, v.w};
        #pragma unroll
        for (int k = 0; k < 4; k++) {
            float f = vals[k];
            if (f >= 0.0f && f <= 1.0f) {        // torch.histc: out-of-range ignored
                int b = (int)(f * 256.0f);       // floor (f >= 0)
                if (b > 255) b = 255;            // f == 1.0 -> last bin
                atomicAdd(&sh[(b << 5) | lane], 1u);
            }
        }
    }
    __syncthreads();

    // Reduce 32 lane-columns per bin; rotate start index so the 32 reads of
    // thread tid stay conflict-free across the warp.
    unsigned int s = 0;
    const unsigned int* row = &sh[tid << 5];
    #pragma unroll
    for (int i = 0; i < 32; i++) s += row[(lane + i) & 31];
    g_hist_partial[((size_t)sample * CHUNKS + chunk) * NBINS + tid] = s;
}

// ---------------------------------------------------------------------------
// Kernel 2: per-sample threshold value + MLP. grid = NB, 128 threads.
// Fully parallel (no serial tid-0 scans).
// ---------------------------------------------------------------------------
__global__ __launch_bounds__(128) void mlp_kernel(
    const float* __restrict__ W1, const float* __restrict__ b1,
    const float* __restrict__ W2, const float* __restrict__ b2,
    const float* __restrict__ W3, const float* __restrict__ b3,
    const float* __restrict__ W4, const float* __restrict__ b4,
    float* __restrict__ out_value)
{
    __shared__ float        s_h[NBINS];
    __shared__ unsigned int s_red[4];
    __shared__ float        s_l1p[4][32];
    __shared__ float        s_h1[32];
    __shared__ float        s_h2[64];
    __shared__ float        s_h3[128];
    __shared__ float        s_p[4];
    __shared__ unsigned int s_key;

    const int b    = blockIdx.x;
    const int tid  = threadIdx.x;   // 0..127
    const int lane = tid & 31;
    const int wrp  = tid >> 5;

    // Sum 16 chunk partials -> histogram (uint counts, exact in float)
    unsigned int cnt[2];
    #pragma unroll
    for (int r = 0; r < 2; r++) {
        const int bin = tid + r * 128;
        unsigned int s = 0;
        const unsigned int* p = &g_hist_partial[(size_t)b * CHUNKS * NBINS + bin];
        #pragma unroll
        for (int c = 0; c < CHUNKS; c++) s += p[c * NBINS];
        cnt[r] = s;
        s_h[bin] = (float)s;
    }

    // First-occurrence argmax via packed key: (count << 8) | (255 - idx).
    // counts <= 262144 < 2^19 -> key fits 27 bits; ties go to LOWEST index.
    unsigned int key = 0;
    #pragma unroll
    for (int r = 0; r < 2; r++) {
        const int bin = tid + r * 128;
        unsigned int k = (cnt[r] << 8) | (unsigned)(255 - bin);
        if (k > key) key = k;
    }
    #pragma unroll
    for (int o = 16; o > 0; o >>= 1) {
        unsigned int other = __shfl_down_sync(0xffffffffu, key, o);
        if (other > key) key = other;
    }
    if (lane == 0) s_red[wrp] = key;
    __syncthreads();
    if (tid == 0) {
        unsigned int k = s_red[0];
        if (s_red[1] > k) k = s_red[1];
        if (s_red[2] > k) k = s_red[2];
        if (s_red[3] > k) k = s_red[3];
        s_key = k;
    }
    __syncthreads();

    const int   am = 255 - (int)(s_key & 255u);
    const float ch = (float)(s_key >> 8) * HEIGHT_RT;

    // First i >= am with h[i] <= ch (cond false); default 0 if none.
    int mini = 0x7fffffff;
    #pragma unroll
    for (int r = 0; r < 2; r++) {
        const int bin = tid + r * 128;
        if (bin >= am && !(s_h[bin] > ch) && bin < mini) mini = bin;
    }
    #pragma unroll
    for (int o = 16; o > 0; o >>= 1) {
        int other = __shfl_down_sync(0xffffffffu, mini, o);
        if (other < mini) mini = other;
    }
    if (lane == 0) s_red[wrp] = (unsigned)mini;
    __syncthreads();
    if (tid == 0) {
        int m = (int)s_red[0];
        if ((int)s_red[1] < m) m = (int)s_red[1];
        if ((int)s_red[2] < m) m = (int)s_red[2];
        if ((int)s_red[3] < m) m = (int)s_red[3];
        if (m == 0x7fffffff) m = 0;
        out_value[b] = (float)m / (float)NBINS;
    }

    // Layer 1: 256 -> 32  (4 partial threads per output)
    {
        const int o = tid & 31, p = tid >> 5;
        float acc = (p == 0) ? b1[o] : 0.0f;
        const float* w = W1 + o * 256 + p * 64;
        const float* h = s_h + p * 64;
        #pragma unroll 8
        for (int k = 0; k < 64; k++) acc = fmaf(h[k], w[k], acc);
        s_l1p[p][o] = acc;
    }
    __syncthreads();
    if (tid < 32)
        s_h1[tid] = fmaxf(s_l1p[0][tid] + s_l1p[1][tid] + s_l1p[2][tid] + s_l1p[3][tid], 0.0f);
    __syncthreads();

    // Layer 2: 32 -> 64
    if (tid < 64) {
        float acc = b2[tid];
        const float* w = W2 + tid * 32;
        #pragma unroll
        for (int k = 0; k < 32; k++) acc = fmaf(s_h1[k], w[k], acc);
        s_h2[tid] = fmaxf(acc, 0.0f);
    }
    __syncthreads();

    // Layer 3: 64 -> 128
    {
        float acc = b3[tid];
        const float* w = W3 + tid * 64;
        #pragma unroll
        for (int k = 0; k < 64; k++) acc = fmaf(s_h2[k], w[k], acc);
        s_h3[tid] = fmaxf(acc, 0.0f);
    }
    __syncthreads();

    // Layer 4: 128 -> 1
    float part = s_h3[tid] * W4[tid];
    #pragma unroll
    for (int o = 16; o > 0; o >>= 1)
        part += __shfl_down_sync(0xffffffffu, part, o);
    if (lane == 0) s_p[wrp] = part;
    __syncthreads();
    if (tid == 0)
        g_w[b] = s_p[0] + s_p[1] + s_p[2] + s_p[3] + b4[0];
}

// ---------------------------------------------------------------------------
// Kernel 3: out = x * w[sample]. grid = NB*64 blocks, 256 threads, float4 x4.
// Streaming loads/stores: last touch of x, write-once of out.
// ---------------------------------------------------------------------------
__global__ __launch_bounds__(256) void scale_kernel(const float* __restrict__ x,
                                                    float* __restrict__ out)
{
    const int bid    = blockIdx.x;
    const int sample = bid >> 6;                  // 64 blocks per sample
    const float w    = g_w[sample];

    const size_t base = (size_t)bid * 1024 + threadIdx.x;
    const float4* __restrict__ xin = (const float4*)x   + base;
    float4* __restrict__       o   = (float4*)out       + base;
    #pragma unroll
    for (int j = 0; j < 4; j++) {
        float4 v = __ldcs(xin + j * 256);
        v.x *= w; v.y *= w; v.z *= w; v.w *= w;
        __stcs(o + j * 256, v);
    }
}

// ---------------------------------------------------------------------------
extern "C" void kernel_launch(void* const* d_in, const int* in_sizes, int n_in,
                              void* d_out, int out_size)
{
    const float* x  = (const float*)d_in[0];
    const float* W1 = (const float*)d_in[1];
    const float* b1 = (const float*)d_in[2];
    const float* W2 = (const float*)d_in[3];
    const float* b2 = (const float*)d_in[4];
    const float* W3 = (const float*)d_in[5];
    const float* b3 = (const float*)d_in[6];
    const float* W4 = (const float*)d_in[7];
    const float* b4 = (const float*)d_in[8];

    float* out       = (float*)d_out;
    float* out_value = out + OUT_X;

    dim3 hgrid(CHUNKS, NB);
    hist_kernel<<<hgrid, 256>>>(x);
    mlp_kernel<<<NB, 128>>>(W1, b1, W2, b2, W3, b3, W4, b4, out_value);
    scale_kernel<<<NB * 64, 256>>>(x, out);
    (void)in_sizes; (void)n_in; (void)out_size;
}